// round 9
// baseline (speedup 1.0000x reference)
#include <cuda_runtime.h>
#include <cuda_fp16.h>
#include <math.h>

#define NB 4
#define NC 128
#define NH 256
#define NW 256
#define NHW (NH*NW)
#define NBC (NB*NC)      // 512 (b,c) planes
#define CM 16
#define PYR_ELEMS 21844  // 128^2+64^2+32^2+16^2+8^2+4^2+2^2

// scratch (device globals: no allocation allowed)
__device__ float   g_thr[2*NBC];
__device__ __half2 g_M0[(size_t)NBC*NHW];        // (pos,neg) packed: max(init, down0)
__device__ __half2 g_r1[(size_t)NBC*128*128];    // resize(down0 -> 128) both signs
__device__ float2  g_pyr[(size_t)NBC*PYR_ELEMS]; // levels 1..7 fp32 (chain precision)
__device__ __half2 g_pyrh[(size_t)NBC*PYR_ELEMS];// same, half2 (consumer copy)
__device__ __half  g_rad[(size_t)NBC*NHW];       // radiance = Lp - Ln

__device__ __constant__ float c_scf[7] = {
    (float)(127.0/255.0), (float)(63.0/255.0), (float)(31.0/255.0),
    (float)(15.0/255.0),  (float)(7.0/255.0),  (float)(3.0/255.0),
    (float)(1.0/255.0)
};
__device__ __constant__ int c_soff[7] = {0, 0, 4096, 5120, 5376, 5440, 5456}; // spyr offsets (k>=1)

__device__ __forceinline__ float sigmoid_f(float t) { return 1.0f / (1.0f + __expf(-t)); }

// ---- packed f32x2 helpers (dual-lane fp32; bitwise identical to 2x scalar) ----
__device__ __forceinline__ unsigned long long pk2(float lo, float hi) {
    unsigned long long r;
    asm("mov.b64 %0, {%1, %2};" : "=l"(r) : "f"(lo), "f"(hi));
    return r;
}
__device__ __forceinline__ void upk2(float& lo, float& hi, unsigned long long v) {
    asm("mov.b64 {%0, %1}, %2;" : "=f"(lo), "=f"(hi) : "l"(v));
}
__device__ __forceinline__ unsigned long long fma2(unsigned long long a,
                                                   unsigned long long b,
                                                   unsigned long long c) {
    unsigned long long r;
    asm("fma.rn.f32x2 %0, %1, %2, %3;" : "=l"(r) : "l"(a), "l"(b), "l"(c));
    return r;
}

// ------------------------------------------------------------------ K0: stats
__global__ void __launch_bounds__(256) k_stats(const float* __restrict__ x) {
    int plane = blockIdx.x;
    const float4* p = (const float4*)(x + (size_t)plane * NHW);
    float sp = 0.f, s2p = 0.f, sn = 0.f, s2n = 0.f;
    for (int i = threadIdx.x; i < NHW/4; i += 256) {
        float4 v = __ldg(p + i);
        float a;
        a = fmaxf(v.x,0.f); sp += a; s2p = fmaf(a,a,s2p); a = fmaxf(-v.x,0.f); sn += a; s2n = fmaf(a,a,s2n);
        a = fmaxf(v.y,0.f); sp += a; s2p = fmaf(a,a,s2p); a = fmaxf(-v.y,0.f); sn += a; s2n = fmaf(a,a,s2n);
        a = fmaxf(v.z,0.f); sp += a; s2p = fmaf(a,a,s2p); a = fmaxf(-v.z,0.f); sn += a; s2n = fmaf(a,a,s2n);
        a = fmaxf(v.w,0.f); sp += a; s2p = fmaf(a,a,s2p); a = fmaxf(-v.w,0.f); sn += a; s2n = fmaf(a,a,s2n);
    }
    __shared__ float red[8][4];
    #pragma unroll
    for (int o = 16; o; o >>= 1) {
        sp  += __shfl_down_sync(0xffffffffu, sp,  o);
        s2p += __shfl_down_sync(0xffffffffu, s2p, o);
        sn  += __shfl_down_sync(0xffffffffu, sn,  o);
        s2n += __shfl_down_sync(0xffffffffu, s2n, o);
    }
    int lane = threadIdx.x & 31, w = threadIdx.x >> 5;
    if (lane == 0) { red[w][0] = sp; red[w][1] = s2p; red[w][2] = sn; red[w][3] = s2n; }
    __syncthreads();
    if (threadIdx.x == 0) {
        float SP=0,S2P=0,SN=0,S2N=0;
        for (int i = 0; i < 8; i++) { SP+=red[i][0]; S2P+=red[i][1]; SN+=red[i][2]; S2N+=red[i][3]; }
        const float N = (float)NHW;
        float vp = fmaxf((S2P - SP*SP/N) / (N - 1.f), 0.f);
        g_thr[plane]       = SP/N + 2.f * sqrtf(vp);
        float vn = fmaxf((S2N - SN*SN/N) / (N - 1.f), 0.f);
        g_thr[NBC + plane] = SN/N + 2.f * sqrtf(vn);
    }
}

// -------------------------------------------------- K1: init + M0 + r1 samples
__global__ void __launch_bounds__(256) k_init(const float* __restrict__ x) {
    __shared__ float ip[35][36], inn[35][36];   // init with halo rows ty0-1 .. ty0+33
    __shared__ float dp[33][36], dn[33][36];    // down0 rows ty0 .. ty0+32
    const int bc  = blockIdx.z;
    const int tx0 = blockIdx.x * 32, ty0 = blockIdx.y * 32;
    const float thp = g_thr[bc], thn = g_thr[NBC + bc];
    const float* xp = x + (size_t)bc * NHW;
    const int tid = threadIdx.x;

    for (int idx = tid; idx < 35*35; idx += 256) {
        int r = idx / 35, c = idx % 35;
        int gy = ty0 - 1 + r; gy = min(max(gy, 0), NH-1);
        int gx = tx0 - 1 + c; gx = min(max(gx, 0), NW-1);
        float v  = __ldg(xp + gy*NW + gx);
        float vp = fmaxf(v, 0.f);
        float vn = fmaxf(-v, 0.f);
        ip[r][c]  = vp * (sigmoid_f(100.f*(vp - thp)) + 1e-6f);
        inn[r][c] = vn * (sigmoid_f(100.f*(vn - thn)) + 1e-6f);
    }
    __syncthreads();
    for (int idx = tid; idx < 33*33; idx += 256) {
        int r = idx / 33, c = idx % 33;
        float mp = 0.f, mn = 0.f;
        #pragma unroll
        for (int dr = 0; dr < 3; dr++)
        #pragma unroll
        for (int dc = 0; dc < 3; dc++) {
            mp = fmaxf(mp, ip[r+dr][c+dc]);
            mn = fmaxf(mn, inn[r+dr][c+dc]);
        }
        dp[r][c] = 0.99f * mp;
        dn[r][c] = 0.99f * mn;
    }
    __syncthreads();
    for (int idx = tid; idx < 32*32; idx += 256) {
        int r = idx >> 5, c = idx & 31;
        float m0p = fmaxf(ip[r+1][c+1], dp[r][c]);
        float m0n = fmaxf(inn[r+1][c+1], dn[r][c]);
        g_M0[(size_t)bc*NHW + (size_t)(ty0+r)*NW + (tx0+c)] = __floats2half2_rn(m0p, m0n);
    }
    // r1 = resize(down0 -> 128, align_corners). Tile owns (i,j) iff floor(i*A1)
    // in [ty0,ty0+31] and floor(j*A1) in [tx0,tx0+31] (same fp expr as below).
    const float A1 = 255.0f / 127.0f;
    int i_lo = max(0, (int)((float)ty0 / A1) - 1);
    while (i_lo < 128 && (int)((float)i_lo * A1) < ty0) i_lo++;
    int i_hi = min(127, (int)((float)(ty0+32) / A1) + 1);
    while (i_hi >= i_lo && (int)((float)i_hi * A1) > ty0+31) i_hi--;
    int j_lo = max(0, (int)((float)tx0 / A1) - 1);
    while (j_lo < 128 && (int)((float)j_lo * A1) < tx0) j_lo++;
    int j_hi = min(127, (int)((float)(tx0+32) / A1) + 1);
    while (j_hi >= j_lo && (int)((float)j_hi * A1) > tx0+31) j_hi--;
    int ni = i_hi - i_lo + 1; if (ni < 0) ni = 0;
    int nj = j_hi - j_lo + 1; if (nj < 0) nj = 0;
    for (int idx = tid; idx < ni*nj; idx += 256) {
        int i = i_lo + idx / nj;
        int j = j_lo + idx % nj;
        float fy = (float)i * A1; int i0 = (int)fy; float wy = fy - (float)i0;
        int i1 = min(i0 + 1, NH-1);
        float fx = (float)j * A1; int j0 = (int)fx; float wx = fx - (float)j0;
        int j1 = min(j0 + 1, NW-1);
        int li0 = i0 - ty0, li1 = i1 - ty0, lj0 = j0 - tx0, lj1 = j1 - tx0;
        float vp = (1.f-wy)*((1.f-wx)*dp[li0][lj0] + wx*dp[li0][lj1])
                 +      wy *((1.f-wx)*dp[li1][lj0] + wx*dp[li1][lj1]);
        float vn = (1.f-wy)*((1.f-wx)*dn[li0][lj0] + wx*dn[li0][lj1])
                 +      wy *((1.f-wx)*dn[li1][lj0] + wx*dn[li1][lj1]);
        g_r1[(size_t)bc*16384 + i*128 + j] = __floats2half2_rn(vp, vn);
    }
}

// ----------------------------------------------- K2: pyramid levels 1..7 (fp32 chain)
#define SMEM_PYR (16384*4 + 4096*8)   // S: 16384 half2, R: 4096 float2
__global__ void __launch_bounds__(256) k_pyr() {
    extern __shared__ unsigned char smraw[];
    __half2* S = (__half2*)smraw;                 // r1 staging
    float2*  R = (float2*)(smraw + 16384*4);      // resize buffer (<= 64x64)
    const int bc = blockIdx.x, tid = threadIdx.x;
    const __half2* r1p = g_r1 + (size_t)bc * 16384;
    float2*  pyr  = g_pyr  + (size_t)bc * PYR_ELEMS;
    __half2* pyrh = g_pyrh + (size_t)bc * PYR_ELEMS;

    for (int i = tid; i < 16384; i += 256) S[i] = __ldg(r1p + i);
    __syncthreads();
    // level 1 (size 128): down1 = gamma^2 * maxpool3(r1)
    for (int idx = tid; idx < 16384; idx += 256) {
        int i = idx >> 7, j = idx & 127;
        float mp = 0.f, mn = 0.f;
        #pragma unroll
        for (int dr = -1; dr <= 1; dr++) {
            int ii = min(max(i+dr,0),127) << 7;
            #pragma unroll
            for (int dc = -1; dc <= 1; dc++) {
                int jj = min(max(j+dc,0),127);
                float2 v = __half22float2(S[ii + jj]);
                mp = fmaxf(mp, v.x); mn = fmaxf(mn, v.y);
            }
        }
        float op = 0.9801f*mp, on = 0.9801f*mn;
        pyr[idx]  = make_float2(op, on);
        pyrh[idx] = __floats2half2_rn(op, on);
    }
    __syncthreads();   // block-visible gmem writes
    int off_in = 0, off_out = 16384, sin = 128;
    double gd = 0.9801;
    for (int k = 2; k <= 7; k++) {
        int sout = sin >> 1;
        float ak = (float)((double)(sin-1) / (double)(sout-1));
        const float2* Lv = pyr + off_in;
        for (int idx = tid; idx < sout*sout; idx += 256) {
            int i = idx / sout, j = idx % sout;
            float fy = (float)i * ak; int i0 = (int)fy; float wy = fy - (float)i0; int i1 = min(i0+1, sin-1);
            float fx = (float)j * ak; int j0 = (int)fx; float wx = fx - (float)j0; int j1 = min(j0+1, sin-1);
            float2 a = Lv[i0*sin+j0], b = Lv[i0*sin+j1], c = Lv[i1*sin+j0], d = Lv[i1*sin+j1];
            R[idx] = make_float2(
                (1.f-wy)*((1.f-wx)*a.x + wx*b.x) + wy*((1.f-wx)*c.x + wx*d.x),
                (1.f-wy)*((1.f-wx)*a.y + wx*b.y) + wy*((1.f-wx)*c.y + wx*d.y));
        }
        __syncthreads();
        gd *= gd;                         // gamma^(2^k)
        float gk = (float)gd;
        for (int idx = tid; idx < sout*sout; idx += 256) {
            int i = idx / sout, j = idx % sout;
            float mp = 0.f, mn = 0.f;
            #pragma unroll
            for (int dr = -1; dr <= 1; dr++) {
                int ii = min(max(i+dr,0),sout-1) * sout;
                #pragma unroll
                for (int dc = -1; dc <= 1; dc++) {
                    int jj = min(max(j+dc,0),sout-1);
                    float2 v = R[ii + jj];
                    mp = fmaxf(mp, v.x); mn = fmaxf(mn, v.y);
                }
            }
            float op = gk*mp, on = gk*mn;
            pyr[off_out + idx]  = make_float2(op, on);
            pyrh[off_out + idx] = __floats2half2_rn(op, on);
        }
        __syncthreads();
        off_in = off_out; off_out += sout*sout; sin = sout;
    }
}

// ----- K3: radiance. Pair-packed rowbuf: 1 LDS.64 per level per pixel (7 total)
#define SMEM_RB (2*8*256*8)   // [2 buf][8 rows][256 pair slots] of uint2
__global__ void __launch_bounds__(256, 4) k_field() {
    __shared__ __half2 spyr[5460];       // levels 2..7 (64^2..2^2)
    extern __shared__ uint2 rbp[];       // pair rowbuf: slot j = (v[j], v[j+1])
    unsigned* rbw = (unsigned*)rbp;      // 32-bit view for builders
    const int bc  = blockIdx.x;
    const int tid = threadIdx.x;
    const __half2* pyrh = g_pyrh + (size_t)bc * PYR_ELEMS;
    for (int i = tid; i < 5460; i += 256) spyr[i] = __ldg(&pyrh[16384 + i]);

    // consume constants: pair-slot index per level (taps come as one LDS.64)
    const int rboff[7] = {0, 128, 192, 224, 240, 248, 252};
    int j0a[7]; __half2 w2a[7], om2a[7];
    #pragma unroll
    for (int k = 0; k < 7; k++) {
        float fx = (float)tid * c_scf[k];
        int j0 = (int)fx; float wx = fx - (float)j0;
        j0a[k] = rboff[k] + j0;
        w2a[k]  = __floats2half2_rn(wx, wx);
        om2a[k] = __floats2half2_rn(1.f-wx, 1.f-wx);
    }

    // build constants: thread tid builds value at (level kb, index jb)
    int kb, jb;
    if      (tid < 128) { kb = 0; jb = tid;       }
    else if (tid < 192) { kb = 1; jb = tid - 128; }
    else if (tid < 224) { kb = 2; jb = tid - 192; }
    else if (tid < 240) { kb = 3; jb = tid - 224; }
    else if (tid < 248) { kb = 4; jb = tid - 240; }
    else if (tid < 252) { kb = 5; jb = tid - 248; }
    else                { kb = 6; jb = tid - 252; }
    const bool doB = (tid < 254);
    const int   sb   = 128 >> kb;
    const float scb  = c_scf[kb];
    const int   sob  = c_soff[kb];
    const int   bpos = rboff[kb] + jb;      // pair-slot this thread owns (lo half)
    const bool  isLast = (jb == sb-1);
    __syncthreads();   // spyr visible

    // y-lerped value (half2 math) for output row y at (kb, jb)
    auto buildv = [&](int y) -> unsigned {
        float fy = (float)y * scb;
        int i0 = (int)fy; float wy = fy - (float)i0; int i1 = min(i0+1, sb-1);
        __half2 a, b;
        if (kb == 0) { a = __ldg(&pyrh[i0*128 + jb]); b = __ldg(&pyrh[i1*128 + jb]); }
        else         { a = spyr[sob + i0*sb + jb];    b = spyr[sob + i1*sb + jb];    }
        __half2 v = __hfma2(__float2half2_rn(wy), b,
                            __hmul2(__float2half2_rn(1.f-wy), a));
        return *(unsigned*)&v;
    };
    // write v into pair slots: own .lo, previous slot's .hi, clamp dup at edge
    auto storev = [&](int rowbase /*pairs*/, unsigned vb) {
        int w = (rowbase + bpos) * 2;
        rbw[w] = vb;
        if (jb > 0)  rbw[w - 1] = vb;      // (bpos-1).hi
        if (isLast)  rbw[w + 1] = vb;      // own .hi (j1 clamp)
    };

    // prologue: rows 0..7 into buffer 0
    if (doB) {
        #pragma unroll
        for (int r = 0; r < 8; r++) storev(r*256, buildv(r));
    }
    __syncthreads();

    const __half2* M0p = g_M0 + (size_t)bc * NHW + tid;
    __half* radp = g_rad + (size_t)bc * NHW + tid;
    const __half2 h2z = __floats2half2_rn(0.f, 0.f);

    int buf = 0;
    for (int y0 = 0; y0 < NH; y0 += 8) {
        // prefetch next block's build values (loads overlap consume below)
        unsigned nb[8];
        const bool more = (y0 + 8 < NH);
        if (more && doB) {
            #pragma unroll
            for (int r = 0; r < 8; r++) nb[r] = buildv(y0 + 8 + r);
        }
        // consume 8 rows at column tid; two accumulators for ILP
        #pragma unroll
        for (int r = 0; r < 8; r++) {
            const uint2* rowp = rbp + (buf*8 + r)*256;
            __half2 U1 = __ldg(M0p + (y0+r)*NW);   // fields >= 0
            __half2 U2 = h2z;
            #pragma unroll
            for (int k = 0; k < 7; k++) {
                uint2 pr = rowp[j0a[k]];
                __half2 a = *(__half2*)&pr.x;
                __half2 b = *(__half2*)&pr.y;
                __half2 v = __hfma2(w2a[k], b, __hmul2(om2a[k], a));
                if (k & 1) U2 = __hmax2(U2, v); else U1 = __hmax2(U1, v);
            }
            float2 uf = __half22float2(__hmax2(U1, U2));
            radp[(y0+r)*NW] = __float2half_rn(uf.x - uf.y);
        }
        if (more && doB) {
            int nbase = (buf^1)*8*256;
            #pragma unroll
            for (int r = 0; r < 8; r++) storev(nbase + r*256, nb[r]);
        }
        __syncthreads();
        buf ^= 1;
    }
}

// ------------- K4: 1x1-conv MLP + modulate (2 px/thread, packed f32x2 FMA)
__global__ void __launch_bounds__(256) k_mlp(
    const float* __restrict__ x,
    const float* __restrict__ w1, const float* __restrict__ b1,
    const float* __restrict__ w2, const float* __restrict__ b2,
    float* __restrict__ out)
{
    __shared__ unsigned long long sw1p[CM*NC];   // (w,w) packed
    __shared__ unsigned long long sw2p[NC*CM];
    __shared__ float sb1[CM], sb2[NC];
    const int tid = threadIdx.x;
    for (int i = tid; i < CM*NC; i += 256) {
        float a = w1[i]; sw1p[i] = pk2(a, a);
        float b = w2[i]; sw2p[i] = pk2(b, b);
    }
    if (tid < CM) sb1[tid] = b1[tid];
    if (tid < NC) sb2[tid] = b2[tid];
    __syncthreads();

    int g  = blockIdx.x * 256 + tid;      // pixel-pair index (131072 total)
    int b  = g >> 15;                     // 32768 pairs per batch
    int hw = (g & 32767) << 1;
    size_t base = ((size_t)(b*NC) << 16) + hw;
    const __half2* rp = (const __half2*)(g_rad + base);
    const float2*  xp = (const float2*) (x     + base);
    float2*        op = (float2*)       (out   + base);

    unsigned long long acc[CM];
    #pragma unroll
    for (int o = 0; o < CM; o++) acc[o] = pk2(sb1[o], sb1[o]);
    for (int c = 0; c < NC; c++) {
        float2 r = __half22float2(__ldg(rp + ((size_t)c << 15)));
        unsigned long long rv = pk2(r.x, r.y);
        #pragma unroll
        for (int o = 0; o < CM; o++)
            acc[o] = fma2(sw1p[o*NC + c], rv, acc[o]);
    }
    #pragma unroll
    for (int o = 0; o < CM; o++) {         // relu (unpack/repack)
        float lo, hi; upk2(lo, hi, acc[o]);
        acc[o] = pk2(fmaxf(lo, 0.f), fmaxf(hi, 0.f));
    }
    for (int c = 0; c < NC; c++) {
        unsigned long long a2 = pk2(sb2[c], sb2[c]);
        #pragma unroll
        for (int o = 0; o < CM; o++)
            a2 = fma2(sw2p[c*CM + o], acc[o], a2);
        float a0, a1; upk2(a0, a1, a2);
        float2 xv = __ldg(xp + ((size_t)c << 15));
        float2 ov;
        ov.x = xv.x * sigmoid_f(a0);
        ov.y = xv.y * sigmoid_f(a1);
        op[(size_t)c << 15] = ov;
    }
}

extern "C" void kernel_launch(void* const* d_in, const int* in_sizes, int n_in,
                              void* d_out, int out_size) {
    const float* x  = (const float*)d_in[0];
    const float* w1 = (const float*)d_in[1];
    const float* b1 = (const float*)d_in[2];
    const float* w2 = (const float*)d_in[3];
    const float* b2 = (const float*)d_in[4];
    float* out = (float*)d_out;

    cudaFuncSetAttribute(k_pyr,   cudaFuncAttributeMaxDynamicSharedMemorySize, SMEM_PYR);
    cudaFuncSetAttribute(k_field, cudaFuncAttributeMaxDynamicSharedMemorySize, SMEM_RB);

    k_stats<<<NBC, 256>>>(x);
    k_init<<<dim3(8, 8, NBC), 256>>>(x);
    k_pyr<<<NBC, 256, SMEM_PYR>>>();
    k_field<<<NBC, 256, SMEM_RB>>>();
    k_mlp<<<(NB*NHW)/512, 256>>>(x, w1, b1, w2, b2, out);
}

// round 10
// speedup vs baseline: 1.1504x; 1.1504x over previous
#include <cuda_runtime.h>
#include <cuda_fp16.h>
#include <math.h>

#define NB 4
#define NC 128
#define NH 256
#define NW 256
#define NHW (NH*NW)
#define NBC (NB*NC)      // 512 (b,c) planes
#define CM 16
#define PYR_ELEMS 21844  // 128^2+64^2+32^2+16^2+8^2+4^2+2^2

// scratch (device globals: no allocation allowed)
__device__ float   g_thr[2*NBC];
__device__ __half2 g_M0[(size_t)NBC*NHW];        // (pos,neg) packed: max(init, down0)
__device__ __half2 g_r1[(size_t)NBC*128*128];    // resize(down0 -> 128) both signs
__device__ float2  g_pyr[(size_t)NBC*PYR_ELEMS]; // levels 1..7 fp32 (chain precision)
__device__ __half2 g_pyrh[(size_t)NBC*PYR_ELEMS];// same, half2 (consumer copy)
__device__ __half  g_rad[(size_t)NBC*NHW];       // radiance = Lp - Ln

__device__ __constant__ float c_scf[7] = {
    (float)(127.0/255.0), (float)(63.0/255.0), (float)(31.0/255.0),
    (float)(15.0/255.0),  (float)(7.0/255.0),  (float)(3.0/255.0),
    (float)(1.0/255.0)
};
__device__ __constant__ int c_soff[7] = {0, 0, 4096, 5120, 5376, 5440, 5456}; // spyr offsets (k>=1)

__device__ __forceinline__ float sigmoid_f(float t) { return 1.0f / (1.0f + __expf(-t)); }

// ------------------------------------------------------------------ K0: stats
__global__ void __launch_bounds__(256) k_stats(const float* __restrict__ x) {
    int plane = blockIdx.x;
    const float4* p = (const float4*)(x + (size_t)plane * NHW);
    float sp = 0.f, s2p = 0.f, sn = 0.f, s2n = 0.f;
    for (int i = threadIdx.x; i < NHW/4; i += 256) {
        float4 v = __ldg(p + i);
        float a;
        a = fmaxf(v.x,0.f); sp += a; s2p = fmaf(a,a,s2p); a = fmaxf(-v.x,0.f); sn += a; s2n = fmaf(a,a,s2n);
        a = fmaxf(v.y,0.f); sp += a; s2p = fmaf(a,a,s2p); a = fmaxf(-v.y,0.f); sn += a; s2n = fmaf(a,a,s2n);
        a = fmaxf(v.z,0.f); sp += a; s2p = fmaf(a,a,s2p); a = fmaxf(-v.z,0.f); sn += a; s2n = fmaf(a,a,s2n);
        a = fmaxf(v.w,0.f); sp += a; s2p = fmaf(a,a,s2p); a = fmaxf(-v.w,0.f); sn += a; s2n = fmaf(a,a,s2n);
    }
    __shared__ float red[8][4];
    #pragma unroll
    for (int o = 16; o; o >>= 1) {
        sp  += __shfl_down_sync(0xffffffffu, sp,  o);
        s2p += __shfl_down_sync(0xffffffffu, s2p, o);
        sn  += __shfl_down_sync(0xffffffffu, sn,  o);
        s2n += __shfl_down_sync(0xffffffffu, s2n, o);
    }
    int lane = threadIdx.x & 31, w = threadIdx.x >> 5;
    if (lane == 0) { red[w][0] = sp; red[w][1] = s2p; red[w][2] = sn; red[w][3] = s2n; }
    __syncthreads();
    if (threadIdx.x == 0) {
        float SP=0,S2P=0,SN=0,S2N=0;
        for (int i = 0; i < 8; i++) { SP+=red[i][0]; S2P+=red[i][1]; SN+=red[i][2]; S2N+=red[i][3]; }
        const float N = (float)NHW;
        float vp = fmaxf((S2P - SP*SP/N) / (N - 1.f), 0.f);
        g_thr[plane]       = SP/N + 2.f * sqrtf(vp);
        float vn = fmaxf((S2N - SN*SN/N) / (N - 1.f), 0.f);
        g_thr[NBC + plane] = SN/N + 2.f * sqrtf(vn);
    }
}

// -------------------------------------------------- K1: init + M0 + r1 samples
__global__ void __launch_bounds__(256) k_init(const float* __restrict__ x) {
    __shared__ float ip[35][36], inn[35][36];   // init with halo rows ty0-1 .. ty0+33
    __shared__ float dp[33][36], dn[33][36];    // down0 rows ty0 .. ty0+32
    const int bc  = blockIdx.z;
    const int tx0 = blockIdx.x * 32, ty0 = blockIdx.y * 32;
    const float thp = g_thr[bc], thn = g_thr[NBC + bc];
    const float* xp = x + (size_t)bc * NHW;
    const int tid = threadIdx.x;

    for (int idx = tid; idx < 35*35; idx += 256) {
        int r = idx / 35, c = idx % 35;
        int gy = ty0 - 1 + r; gy = min(max(gy, 0), NH-1);
        int gx = tx0 - 1 + c; gx = min(max(gx, 0), NW-1);
        float v  = __ldg(xp + gy*NW + gx);
        float vp = fmaxf(v, 0.f);
        float vn = fmaxf(-v, 0.f);
        ip[r][c]  = vp * (sigmoid_f(100.f*(vp - thp)) + 1e-6f);
        inn[r][c] = vn * (sigmoid_f(100.f*(vn - thn)) + 1e-6f);
    }
    __syncthreads();
    for (int idx = tid; idx < 33*33; idx += 256) {
        int r = idx / 33, c = idx % 33;
        float mp = 0.f, mn = 0.f;
        #pragma unroll
        for (int dr = 0; dr < 3; dr++)
        #pragma unroll
        for (int dc = 0; dc < 3; dc++) {
            mp = fmaxf(mp, ip[r+dr][c+dc]);
            mn = fmaxf(mn, inn[r+dr][c+dc]);
        }
        dp[r][c] = 0.99f * mp;
        dn[r][c] = 0.99f * mn;
    }
    __syncthreads();
    for (int idx = tid; idx < 32*32; idx += 256) {
        int r = idx >> 5, c = idx & 31;
        float m0p = fmaxf(ip[r+1][c+1], dp[r][c]);
        float m0n = fmaxf(inn[r+1][c+1], dn[r][c]);
        g_M0[(size_t)bc*NHW + (size_t)(ty0+r)*NW + (tx0+c)] = __floats2half2_rn(m0p, m0n);
    }
    // r1 = resize(down0 -> 128, align_corners). Tile owns (i,j) iff floor(i*A1)
    // in [ty0,ty0+31] and floor(j*A1) in [tx0,tx0+31] (same fp expr as below).
    const float A1 = 255.0f / 127.0f;
    int i_lo = max(0, (int)((float)ty0 / A1) - 1);
    while (i_lo < 128 && (int)((float)i_lo * A1) < ty0) i_lo++;
    int i_hi = min(127, (int)((float)(ty0+32) / A1) + 1);
    while (i_hi >= i_lo && (int)((float)i_hi * A1) > ty0+31) i_hi--;
    int j_lo = max(0, (int)((float)tx0 / A1) - 1);
    while (j_lo < 128 && (int)((float)j_lo * A1) < tx0) j_lo++;
    int j_hi = min(127, (int)((float)(tx0+32) / A1) + 1);
    while (j_hi >= j_lo && (int)((float)j_hi * A1) > tx0+31) j_hi--;
    int ni = i_hi - i_lo + 1; if (ni < 0) ni = 0;
    int nj = j_hi - j_lo + 1; if (nj < 0) nj = 0;
    for (int idx = tid; idx < ni*nj; idx += 256) {
        int i = i_lo + idx / nj;
        int j = j_lo + idx % nj;
        float fy = (float)i * A1; int i0 = (int)fy; float wy = fy - (float)i0;
        int i1 = min(i0 + 1, NH-1);
        float fx = (float)j * A1; int j0 = (int)fx; float wx = fx - (float)j0;
        int j1 = min(j0 + 1, NW-1);
        int li0 = i0 - ty0, li1 = i1 - ty0, lj0 = j0 - tx0, lj1 = j1 - tx0;
        float vp = (1.f-wy)*((1.f-wx)*dp[li0][lj0] + wx*dp[li0][lj1])
                 +      wy *((1.f-wx)*dp[li1][lj0] + wx*dp[li1][lj1]);
        float vn = (1.f-wy)*((1.f-wx)*dn[li0][lj0] + wx*dn[li0][lj1])
                 +      wy *((1.f-wx)*dn[li1][lj0] + wx*dn[li1][lj1]);
        g_r1[(size_t)bc*16384 + i*128 + j] = __floats2half2_rn(vp, vn);
    }
}

// ----------------------------------------------- K2: pyramid levels 1..7 (fp32 chain)
#define SMEM_PYR (16384*4 + 4096*8)   // S: 16384 half2, R: 4096 float2
__global__ void __launch_bounds__(256) k_pyr() {
    extern __shared__ unsigned char smraw[];
    __half2* S = (__half2*)smraw;                 // r1 staging
    float2*  R = (float2*)(smraw + 16384*4);      // resize buffer (<= 64x64)
    const int bc = blockIdx.x, tid = threadIdx.x;
    const __half2* r1p = g_r1 + (size_t)bc * 16384;
    float2*  pyr  = g_pyr  + (size_t)bc * PYR_ELEMS;
    __half2* pyrh = g_pyrh + (size_t)bc * PYR_ELEMS;

    for (int i = tid; i < 16384; i += 256) S[i] = __ldg(r1p + i);
    __syncthreads();
    // level 1 (size 128): down1 = gamma^2 * maxpool3(r1)
    for (int idx = tid; idx < 16384; idx += 256) {
        int i = idx >> 7, j = idx & 127;
        float mp = 0.f, mn = 0.f;
        #pragma unroll
        for (int dr = -1; dr <= 1; dr++) {
            int ii = min(max(i+dr,0),127) << 7;
            #pragma unroll
            for (int dc = -1; dc <= 1; dc++) {
                int jj = min(max(j+dc,0),127);
                float2 v = __half22float2(S[ii + jj]);
                mp = fmaxf(mp, v.x); mn = fmaxf(mn, v.y);
            }
        }
        float op = 0.9801f*mp, on = 0.9801f*mn;
        pyr[idx]  = make_float2(op, on);
        pyrh[idx] = __floats2half2_rn(op, on);
    }
    __syncthreads();   // block-visible gmem writes
    int off_in = 0, off_out = 16384, sin = 128;
    double gd = 0.9801;
    for (int k = 2; k <= 7; k++) {
        int sout = sin >> 1;
        float ak = (float)((double)(sin-1) / (double)(sout-1));
        const float2* Lv = pyr + off_in;
        for (int idx = tid; idx < sout*sout; idx += 256) {
            int i = idx / sout, j = idx % sout;
            float fy = (float)i * ak; int i0 = (int)fy; float wy = fy - (float)i0; int i1 = min(i0+1, sin-1);
            float fx = (float)j * ak; int j0 = (int)fx; float wx = fx - (float)j0; int j1 = min(j0+1, sin-1);
            float2 a = Lv[i0*sin+j0], b = Lv[i0*sin+j1], c = Lv[i1*sin+j0], d = Lv[i1*sin+j1];
            R[idx] = make_float2(
                (1.f-wy)*((1.f-wx)*a.x + wx*b.x) + wy*((1.f-wx)*c.x + wx*d.x),
                (1.f-wy)*((1.f-wx)*a.y + wx*b.y) + wy*((1.f-wx)*c.y + wx*d.y));
        }
        __syncthreads();
        gd *= gd;                         // gamma^(2^k)
        float gk = (float)gd;
        for (int idx = tid; idx < sout*sout; idx += 256) {
            int i = idx / sout, j = idx % sout;
            float mp = 0.f, mn = 0.f;
            #pragma unroll
            for (int dr = -1; dr <= 1; dr++) {
                int ii = min(max(i+dr,0),sout-1) * sout;
                #pragma unroll
                for (int dc = -1; dc <= 1; dc++) {
                    int jj = min(max(j+dc,0),sout-1);
                    float2 v = R[ii + jj];
                    mp = fmaxf(mp, v.x); mn = fmaxf(mn, v.y);
                }
            }
            float op = gk*mp, on = gk*mn;
            pyr[off_out + idx]  = make_float2(op, on);
            pyrh[off_out + idx] = __floats2half2_rn(op, on);
        }
        __syncthreads();
        off_in = off_out; off_out += sout*sout; sin = sout;
    }
}

// ----- K3: radiance. Pair-packed rowbuf: 1 LDS.64 per level per pixel (7 total)
#define SMEM_RB (2*8*256*8)   // [2 buf][8 rows][256 pair slots] of uint2
__global__ void __launch_bounds__(256, 4) k_field() {
    __shared__ __half2 spyr[5460];       // levels 2..7 (64^2..2^2)
    extern __shared__ uint2 rbp[];       // pair rowbuf: slot j = (v[j], v[j+1])
    unsigned* rbw = (unsigned*)rbp;      // 32-bit view for builders
    const int bc  = blockIdx.x;
    const int tid = threadIdx.x;
    const __half2* pyrh = g_pyrh + (size_t)bc * PYR_ELEMS;
    for (int i = tid; i < 5460; i += 256) spyr[i] = __ldg(&pyrh[16384 + i]);

    // consume constants: pair-slot index per level (taps come as one LDS.64)
    const int rboff[7] = {0, 128, 192, 224, 240, 248, 252};
    int j0a[7]; __half2 w2a[7], om2a[7];
    #pragma unroll
    for (int k = 0; k < 7; k++) {
        float fx = (float)tid * c_scf[k];
        int j0 = (int)fx; float wx = fx - (float)j0;
        j0a[k] = rboff[k] + j0;
        w2a[k]  = __floats2half2_rn(wx, wx);
        om2a[k] = __floats2half2_rn(1.f-wx, 1.f-wx);
    }

    // build constants: thread tid builds value at (level kb, index jb)
    int kb, jb;
    if      (tid < 128) { kb = 0; jb = tid;       }
    else if (tid < 192) { kb = 1; jb = tid - 128; }
    else if (tid < 224) { kb = 2; jb = tid - 192; }
    else if (tid < 240) { kb = 3; jb = tid - 224; }
    else if (tid < 248) { kb = 4; jb = tid - 240; }
    else if (tid < 252) { kb = 5; jb = tid - 248; }
    else                { kb = 6; jb = tid - 252; }
    const bool doB = (tid < 254);
    const int   sb   = 128 >> kb;
    const float scb  = c_scf[kb];
    const int   sob  = c_soff[kb];
    const int   bpos = rboff[kb] + jb;      // pair-slot this thread owns (lo half)
    const bool  isLast = (jb == sb-1);
    __syncthreads();   // spyr visible

    // y-lerped value (half2 math) for output row y at (kb, jb)
    auto buildv = [&](int y) -> unsigned {
        float fy = (float)y * scb;
        int i0 = (int)fy; float wy = fy - (float)i0; int i1 = min(i0+1, sb-1);
        __half2 a, b;
        if (kb == 0) { a = __ldg(&pyrh[i0*128 + jb]); b = __ldg(&pyrh[i1*128 + jb]); }
        else         { a = spyr[sob + i0*sb + jb];    b = spyr[sob + i1*sb + jb];    }
        __half2 v = __hfma2(__float2half2_rn(wy), b,
                            __hmul2(__float2half2_rn(1.f-wy), a));
        return *(unsigned*)&v;
    };
    // write v into pair slots: own .lo, previous slot's .hi, clamp dup at edge
    auto storev = [&](int rowbase /*pairs*/, unsigned vb) {
        int w = (rowbase + bpos) * 2;
        rbw[w] = vb;
        if (jb > 0)  rbw[w - 1] = vb;      // (bpos-1).hi
        if (isLast)  rbw[w + 1] = vb;      // own .hi (j1 clamp)
    };

    // prologue: rows 0..7 into buffer 0
    if (doB) {
        #pragma unroll
        for (int r = 0; r < 8; r++) storev(r*256, buildv(r));
    }
    __syncthreads();

    const __half2* M0p = g_M0 + (size_t)bc * NHW + tid;
    __half* radp = g_rad + (size_t)bc * NHW + tid;
    const __half2 h2z = __floats2half2_rn(0.f, 0.f);

    int buf = 0;
    for (int y0 = 0; y0 < NH; y0 += 8) {
        // prefetch next block's build values (loads overlap consume below)
        unsigned nb[8];
        const bool more = (y0 + 8 < NH);
        if (more && doB) {
            #pragma unroll
            for (int r = 0; r < 8; r++) nb[r] = buildv(y0 + 8 + r);
        }
        // consume 8 rows at column tid; two accumulators for ILP
        #pragma unroll
        for (int r = 0; r < 8; r++) {
            const uint2* rowp = rbp + (buf*8 + r)*256;
            __half2 U1 = __ldg(M0p + (y0+r)*NW);   // fields >= 0
            __half2 U2 = h2z;
            #pragma unroll
            for (int k = 0; k < 7; k++) {
                uint2 pr = rowp[j0a[k]];
                __half2 a = *(__half2*)&pr.x;
                __half2 b = *(__half2*)&pr.y;
                __half2 v = __hfma2(w2a[k], b, __hmul2(om2a[k], a));
                if (k & 1) U2 = __hmax2(U2, v); else U1 = __hmax2(U1, v);
            }
            float2 uf = __half22float2(__hmax2(U1, U2));
            radp[(y0+r)*NW] = __float2half_rn(uf.x - uf.y);
        }
        if (more && doB) {
            int nbase = (buf^1)*8*256;
            #pragma unroll
            for (int r = 0; r < 8; r++) storev(nbase + r*256, nb[r]);
        }
        __syncthreads();
        buf ^= 1;
    }
}

// --------------------------- K4: 1x1-conv MLP + modulate (2 px/thread, scalar fp32)
__global__ void __launch_bounds__(256) k_mlp(
    const float* __restrict__ x,
    const float* __restrict__ w1, const float* __restrict__ b1,
    const float* __restrict__ w2, const float* __restrict__ b2,
    float* __restrict__ out)
{
    __shared__ float sw1[CM*NC], sw2[NC*CM], sb1[CM], sb2[NC];
    const int tid = threadIdx.x;
    for (int i = tid; i < CM*NC; i += 256) { sw1[i] = w1[i]; sw2[i] = w2[i]; }
    if (tid < CM) sb1[tid] = b1[tid];
    if (tid < NC) sb2[tid] = b2[tid];
    __syncthreads();

    int g  = blockIdx.x * 256 + tid;      // pixel-pair index (131072 total)
    int b  = g >> 15;                     // 32768 pairs per batch
    int hw = (g & 32767) << 1;
    size_t base = ((size_t)(b*NC) << 16) + hw;
    const __half2* rp = (const __half2*)(g_rad + base);
    const float2*  xp = (const float2*) (x     + base);
    float2*        op = (float2*)       (out   + base);

    float h0[CM], h1[CM];
    #pragma unroll
    for (int o = 0; o < CM; o++) { h0[o] = sb1[o]; h1[o] = sb1[o]; }
    for (int c = 0; c < NC; c++) {
        float2 r = __half22float2(__ldg(rp + ((size_t)c << 15)));
        #pragma unroll
        for (int o = 0; o < CM; o++) {
            float w = sw1[o*NC + c];
            h0[o] = fmaf(w, r.x, h0[o]);
            h1[o] = fmaf(w, r.y, h1[o]);
        }
    }
    #pragma unroll
    for (int o = 0; o < CM; o++) { h0[o] = fmaxf(h0[o], 0.f); h1[o] = fmaxf(h1[o], 0.f); }
    for (int c = 0; c < NC; c++) {
        float a0 = sb2[c], a1 = sb2[c];
        #pragma unroll
        for (int o = 0; o < CM; o++) {
            float w = sw2[c*CM + o];
            a0 = fmaf(w, h0[o], a0);
            a1 = fmaf(w, h1[o], a1);
        }
        float2 xv = __ldg(xp + ((size_t)c << 15));
        float2 ov;
        ov.x = xv.x * sigmoid_f(a0);
        ov.y = xv.y * sigmoid_f(a1);
        op[(size_t)c << 15] = ov;
    }
}

extern "C" void kernel_launch(void* const* d_in, const int* in_sizes, int n_in,
                              void* d_out, int out_size) {
    const float* x  = (const float*)d_in[0];
    const float* w1 = (const float*)d_in[1];
    const float* b1 = (const float*)d_in[2];
    const float* w2 = (const float*)d_in[3];
    const float* b2 = (const float*)d_in[4];
    float* out = (float*)d_out;

    cudaFuncSetAttribute(k_pyr,   cudaFuncAttributeMaxDynamicSharedMemorySize, SMEM_PYR);
    cudaFuncSetAttribute(k_field, cudaFuncAttributeMaxDynamicSharedMemorySize, SMEM_RB);

    k_stats<<<NBC, 256>>>(x);
    k_init<<<dim3(8, 8, NBC), 256>>>(x);
    k_pyr<<<NBC, 256, SMEM_PYR>>>();
    k_field<<<NBC, 256, SMEM_RB>>>();
    k_mlp<<<(NB*NHW)/512, 256>>>(x, w1, b1, w2, b2, out);
}

// round 11
// speedup vs baseline: 1.4005x; 1.2175x over previous
#include <cuda_runtime.h>
#include <cuda_fp16.h>
#include <math.h>

#define NB 4
#define NC 128
#define NH 256
#define NW 256
#define NHW (NH*NW)
#define NBC (NB*NC)      // 512 (b,c) planes
#define CM 16
#define PYR_ELEMS 21844  // 128^2+64^2+32^2+16^2+8^2+4^2+2^2

// scratch (device globals: no allocation allowed)
__device__ float   g_thr[2*NBC];
__device__ __half2 g_M0[(size_t)NBC*NHW];        // (pos,neg) packed: max(init, down0)
__device__ __half2 g_r1[(size_t)NBC*128*128];    // resize(down0 -> 128) both signs
__device__ float2  g_pyr[(size_t)NBC*PYR_ELEMS]; // levels 1..7 fp32 (chain precision)
__device__ __half2 g_pyrh[(size_t)NBC*PYR_ELEMS];// same, half2 (consumer copy)
__device__ __half  g_rad[(size_t)NBC*NHW];       // radiance = Lp - Ln

__device__ __constant__ float c_scf[7] = {
    (float)(127.0/255.0), (float)(63.0/255.0), (float)(31.0/255.0),
    (float)(15.0/255.0),  (float)(7.0/255.0),  (float)(3.0/255.0),
    (float)(1.0/255.0)
};
__device__ __constant__ int c_soff[7] = {0, 0, 4096, 5120, 5376, 5440, 5456}; // spyr offsets (k>=1)

__device__ __forceinline__ float sigmoid_f(float t) { return 1.0f / (1.0f + __expf(-t)); }
// 1-MUFU sigmoid: sigmoid(t) = 0.5*tanh(t/2) + 0.5  (tanh.approx: abs err ~2^-11)
__device__ __forceinline__ float sigmoid_fast(float t) {
    float th;
    asm("tanh.approx.f32 %0, %1;" : "=f"(th) : "f"(0.5f * t));
    return fmaf(0.5f, th, 0.5f);
}

// ------------------------------------------------------------------ K0: stats
__global__ void __launch_bounds__(256) k_stats(const float* __restrict__ x) {
    int plane = blockIdx.x;
    const float4* p = (const float4*)(x + (size_t)plane * NHW);
    float sp = 0.f, s2p = 0.f, sn = 0.f, s2n = 0.f;
    for (int i = threadIdx.x; i < NHW/4; i += 256) {
        float4 v = __ldg(p + i);
        float a;
        a = fmaxf(v.x,0.f); sp += a; s2p = fmaf(a,a,s2p); a = fmaxf(-v.x,0.f); sn += a; s2n = fmaf(a,a,s2n);
        a = fmaxf(v.y,0.f); sp += a; s2p = fmaf(a,a,s2p); a = fmaxf(-v.y,0.f); sn += a; s2n = fmaf(a,a,s2n);
        a = fmaxf(v.z,0.f); sp += a; s2p = fmaf(a,a,s2p); a = fmaxf(-v.z,0.f); sn += a; s2n = fmaf(a,a,s2n);
        a = fmaxf(v.w,0.f); sp += a; s2p = fmaf(a,a,s2p); a = fmaxf(-v.w,0.f); sn += a; s2n = fmaf(a,a,s2n);
    }
    __shared__ float red[8][4];
    #pragma unroll
    for (int o = 16; o; o >>= 1) {
        sp  += __shfl_down_sync(0xffffffffu, sp,  o);
        s2p += __shfl_down_sync(0xffffffffu, s2p, o);
        sn  += __shfl_down_sync(0xffffffffu, sn,  o);
        s2n += __shfl_down_sync(0xffffffffu, s2n, o);
    }
    int lane = threadIdx.x & 31, w = threadIdx.x >> 5;
    if (lane == 0) { red[w][0] = sp; red[w][1] = s2p; red[w][2] = sn; red[w][3] = s2n; }
    __syncthreads();
    if (threadIdx.x == 0) {
        float SP=0,S2P=0,SN=0,S2N=0;
        for (int i = 0; i < 8; i++) { SP+=red[i][0]; S2P+=red[i][1]; SN+=red[i][2]; S2N+=red[i][3]; }
        const float N = (float)NHW;
        float vp = fmaxf((S2P - SP*SP/N) / (N - 1.f), 0.f);
        g_thr[plane]       = SP/N + 2.f * sqrtf(vp);
        float vn = fmaxf((S2N - SN*SN/N) / (N - 1.f), 0.f);
        g_thr[NBC + plane] = SN/N + 2.f * sqrtf(vn);
    }
}

// ------------- K1: init + M0 + r1 samples (half2-packed, separable maxpool)
__global__ void __launch_bounds__(256) k_init(const float* __restrict__ x) {
    __shared__ __half2 sI[35][40];   // masked init, rows/cols (ty0-1.., tx0-1..), 35x35 used
    __shared__ __half2 sR[35][40];   // rowmax3: 35 rows x 33 cols (col c -> global tx0+c)
    __shared__ __half2 sD[33][40];   // down0 = gamma*colmax3: 33x33 (r,c -> ty0+r, tx0+c)
    const int bc  = blockIdx.z;
    const int tx0 = blockIdx.x * 32, ty0 = blockIdx.y * 32;
    const float thp = g_thr[bc], thn = g_thr[NBC + bc];
    const float* xp = x + (size_t)bc * NHW;
    const int tid = threadIdx.x;

    for (int idx = tid; idx < 35*35; idx += 256) {
        int r = idx / 35, c = idx % 35;
        int gy = ty0 - 1 + r; gy = min(max(gy, 0), NH-1);
        int gx = tx0 - 1 + c; gx = min(max(gx, 0), NW-1);
        float v  = __ldg(xp + gy*NW + gx);
        float vp = fmaxf(v, 0.f);
        float vn = fmaxf(-v, 0.f);
        float ipv = vp * (sigmoid_fast(100.f*(vp - thp)) + 1e-6f);
        float inv = vn * (sigmoid_fast(100.f*(vn - thn)) + 1e-6f);
        sI[r][c] = __floats2half2_rn(ipv, inv);
    }
    __syncthreads();
    for (int idx = tid; idx < 35*33; idx += 256) {
        int r = idx / 33, c = idx % 33;
        sR[r][c] = __hmax2(__hmax2(sI[r][c], sI[r][c+1]), sI[r][c+2]);
    }
    __syncthreads();
    for (int idx = tid; idx < 33*33; idx += 256) {
        int r = idx / 33, c = idx % 33;
        __half2 m = __hmax2(__hmax2(sR[r][c], sR[r+1][c]), sR[r+2][c]);
        float2 mf = __half22float2(m);
        sD[r][c] = __floats2half2_rn(0.99f*mf.x, 0.99f*mf.y);
    }
    __syncthreads();
    for (int idx = tid; idx < 32*32; idx += 256) {
        int r = idx >> 5, c = idx & 31;
        g_M0[(size_t)bc*NHW + (size_t)(ty0+r)*NW + (tx0+c)] =
            __hmax2(sI[r+1][c+1], sD[r][c]);
    }
    // r1 = resize(down0 -> 128, align_corners). Tile owns (i,j) iff floor(i*A1)
    // in [ty0,ty0+31] and floor(j*A1) in [tx0,tx0+31] (same fp expr as below).
    const float A1 = 255.0f / 127.0f;
    int i_lo = max(0, (int)((float)ty0 / A1) - 1);
    while (i_lo < 128 && (int)((float)i_lo * A1) < ty0) i_lo++;
    int i_hi = min(127, (int)((float)(ty0+32) / A1) + 1);
    while (i_hi >= i_lo && (int)((float)i_hi * A1) > ty0+31) i_hi--;
    int j_lo = max(0, (int)((float)tx0 / A1) - 1);
    while (j_lo < 128 && (int)((float)j_lo * A1) < tx0) j_lo++;
    int j_hi = min(127, (int)((float)(tx0+32) / A1) + 1);
    while (j_hi >= j_lo && (int)((float)j_hi * A1) > tx0+31) j_hi--;
    int ni = i_hi - i_lo + 1; if (ni < 0) ni = 0;
    int nj = j_hi - j_lo + 1; if (nj < 0) nj = 0;
    for (int idx = tid; idx < ni*nj; idx += 256) {
        int i = i_lo + idx / nj;
        int j = j_lo + idx % nj;
        float fy = (float)i * A1; int i0 = (int)fy; float wy = fy - (float)i0;
        int i1 = min(i0 + 1, NH-1);
        float fx = (float)j * A1; int j0 = (int)fx; float wx = fx - (float)j0;
        int j1 = min(j0 + 1, NW-1);
        int li0 = i0 - ty0, li1 = i1 - ty0, lj0 = j0 - tx0, lj1 = j1 - tx0;
        float2 a = __half22float2(sD[li0][lj0]);
        float2 b = __half22float2(sD[li0][lj1]);
        float2 c2 = __half22float2(sD[li1][lj0]);
        float2 d = __half22float2(sD[li1][lj1]);
        float vp = (1.f-wy)*((1.f-wx)*a.x + wx*b.x) + wy*((1.f-wx)*c2.x + wx*d.x);
        float vn = (1.f-wy)*((1.f-wx)*a.y + wx*b.y) + wy*((1.f-wx)*c2.y + wx*d.y);
        g_r1[(size_t)bc*16384 + i*128 + j] = __floats2half2_rn(vp, vn);
    }
}

// ----------------------------------------------- K2: pyramid levels 1..7 (fp32 chain)
#define SMEM_PYR (16384*4 + 4096*8)   // S: 16384 half2, R: 4096 float2
__global__ void __launch_bounds__(256) k_pyr() {
    extern __shared__ unsigned char smraw[];
    __half2* S = (__half2*)smraw;                 // r1 staging
    float2*  R = (float2*)(smraw + 16384*4);      // resize buffer (<= 64x64)
    const int bc = blockIdx.x, tid = threadIdx.x;
    const __half2* r1p = g_r1 + (size_t)bc * 16384;
    float2*  pyr  = g_pyr  + (size_t)bc * PYR_ELEMS;
    __half2* pyrh = g_pyrh + (size_t)bc * PYR_ELEMS;

    for (int i = tid; i < 16384; i += 256) S[i] = __ldg(r1p + i);
    __syncthreads();
    // level 1 (size 128): down1 = gamma^2 * maxpool3(r1)
    for (int idx = tid; idx < 16384; idx += 256) {
        int i = idx >> 7, j = idx & 127;
        float mp = 0.f, mn = 0.f;
        #pragma unroll
        for (int dr = -1; dr <= 1; dr++) {
            int ii = min(max(i+dr,0),127) << 7;
            #pragma unroll
            for (int dc = -1; dc <= 1; dc++) {
                int jj = min(max(j+dc,0),127);
                float2 v = __half22float2(S[ii + jj]);
                mp = fmaxf(mp, v.x); mn = fmaxf(mn, v.y);
            }
        }
        float op = 0.9801f*mp, on = 0.9801f*mn;
        pyr[idx]  = make_float2(op, on);
        pyrh[idx] = __floats2half2_rn(op, on);
    }
    __syncthreads();   // block-visible gmem writes
    int off_in = 0, off_out = 16384, sin = 128;
    double gd = 0.9801;
    for (int k = 2; k <= 7; k++) {
        int sout = sin >> 1;
        float ak = (float)((double)(sin-1) / (double)(sout-1));
        const float2* Lv = pyr + off_in;
        for (int idx = tid; idx < sout*sout; idx += 256) {
            int i = idx / sout, j = idx % sout;
            float fy = (float)i * ak; int i0 = (int)fy; float wy = fy - (float)i0; int i1 = min(i0+1, sin-1);
            float fx = (float)j * ak; int j0 = (int)fx; float wx = fx - (float)j0; int j1 = min(j0+1, sin-1);
            float2 a = Lv[i0*sin+j0], b = Lv[i0*sin+j1], c = Lv[i1*sin+j0], d = Lv[i1*sin+j1];
            R[idx] = make_float2(
                (1.f-wy)*((1.f-wx)*a.x + wx*b.x) + wy*((1.f-wx)*c.x + wx*d.x),
                (1.f-wy)*((1.f-wx)*a.y + wx*b.y) + wy*((1.f-wx)*c.y + wx*d.y));
        }
        __syncthreads();
        gd *= gd;                         // gamma^(2^k)
        float gk = (float)gd;
        for (int idx = tid; idx < sout*sout; idx += 256) {
            int i = idx / sout, j = idx % sout;
            float mp = 0.f, mn = 0.f;
            #pragma unroll
            for (int dr = -1; dr <= 1; dr++) {
                int ii = min(max(i+dr,0),sout-1) * sout;
                #pragma unroll
                for (int dc = -1; dc <= 1; dc++) {
                    int jj = min(max(j+dc,0),sout-1);
                    float2 v = R[ii + jj];
                    mp = fmaxf(mp, v.x); mn = fmaxf(mn, v.y);
                }
            }
            float op = gk*mp, on = gk*mn;
            pyr[off_out + idx]  = make_float2(op, on);
            pyrh[off_out + idx] = __floats2half2_rn(op, on);
        }
        __syncthreads();
        off_in = off_out; off_out += sout*sout; sin = sout;
    }
}

// ----- K3: radiance. Pair-packed rowbuf: 1 LDS.64 per level per pixel (7 total)
#define SMEM_RB (2*8*256*8)   // [2 buf][8 rows][256 pair slots] of uint2
__global__ void __launch_bounds__(256, 4) k_field() {
    __shared__ __half2 spyr[5460];       // levels 2..7 (64^2..2^2)
    extern __shared__ uint2 rbp[];       // pair rowbuf: slot j = (v[j], v[j+1])
    unsigned* rbw = (unsigned*)rbp;      // 32-bit view for builders
    const int bc  = blockIdx.x;
    const int tid = threadIdx.x;
    const __half2* pyrh = g_pyrh + (size_t)bc * PYR_ELEMS;
    for (int i = tid; i < 5460; i += 256) spyr[i] = __ldg(&pyrh[16384 + i]);

    // consume constants: pair-slot index per level (taps come as one LDS.64)
    const int rboff[7] = {0, 128, 192, 224, 240, 248, 252};
    int j0a[7]; __half2 w2a[7], om2a[7];
    #pragma unroll
    for (int k = 0; k < 7; k++) {
        float fx = (float)tid * c_scf[k];
        int j0 = (int)fx; float wx = fx - (float)j0;
        j0a[k] = rboff[k] + j0;
        w2a[k]  = __floats2half2_rn(wx, wx);
        om2a[k] = __floats2half2_rn(1.f-wx, 1.f-wx);
    }

    // build constants: thread tid builds value at (level kb, index jb)
    int kb, jb;
    if      (tid < 128) { kb = 0; jb = tid;       }
    else if (tid < 192) { kb = 1; jb = tid - 128; }
    else if (tid < 224) { kb = 2; jb = tid - 192; }
    else if (tid < 240) { kb = 3; jb = tid - 224; }
    else if (tid < 248) { kb = 4; jb = tid - 240; }
    else if (tid < 252) { kb = 5; jb = tid - 248; }
    else                { kb = 6; jb = tid - 252; }
    const bool doB = (tid < 254);
    const int   sb   = 128 >> kb;
    const float scb  = c_scf[kb];
    const int   sob  = c_soff[kb];
    const int   bpos = rboff[kb] + jb;      // pair-slot this thread owns (lo half)
    const bool  isLast = (jb == sb-1);
    __syncthreads();   // spyr visible

    // y-lerped value (half2 math) for output row y at (kb, jb)
    auto buildv = [&](int y) -> unsigned {
        float fy = (float)y * scb;
        int i0 = (int)fy; float wy = fy - (float)i0; int i1 = min(i0+1, sb-1);
        __half2 a, b;
        if (kb == 0) { a = __ldg(&pyrh[i0*128 + jb]); b = __ldg(&pyrh[i1*128 + jb]); }
        else         { a = spyr[sob + i0*sb + jb];    b = spyr[sob + i1*sb + jb];    }
        __half2 v = __hfma2(__float2half2_rn(wy), b,
                            __hmul2(__float2half2_rn(1.f-wy), a));
        return *(unsigned*)&v;
    };
    // write v into pair slots: own .lo, previous slot's .hi, clamp dup at edge
    auto storev = [&](int rowbase /*pairs*/, unsigned vb) {
        int w = (rowbase + bpos) * 2;
        rbw[w] = vb;
        if (jb > 0)  rbw[w - 1] = vb;      // (bpos-1).hi
        if (isLast)  rbw[w + 1] = vb;      // own .hi (j1 clamp)
    };

    // prologue: rows 0..7 into buffer 0
    if (doB) {
        #pragma unroll
        for (int r = 0; r < 8; r++) storev(r*256, buildv(r));
    }
    __syncthreads();

    const __half2* M0p = g_M0 + (size_t)bc * NHW + tid;
    __half* radp = g_rad + (size_t)bc * NHW + tid;

    int buf = 0;
    for (int y0 = 0; y0 < NH; y0 += 8) {
        // batch-issue this block's 8 M0 loads (MLP=8 hides L2/DRAM latency)
        __half2 m0v[8];
        #pragma unroll
        for (int r = 0; r < 8; r++) m0v[r] = __ldg(M0p + (y0+r)*NW);
        // prefetch next block's build values (loads overlap consume below)
        unsigned nb[8];
        const bool more = (y0 + 8 < NH);
        if (more && doB) {
            #pragma unroll
            for (int r = 0; r < 8; r++) nb[r] = buildv(y0 + 8 + r);
        }
        // consume 8 rows at column tid; two accumulators for ILP
        #pragma unroll
        for (int r = 0; r < 8; r++) {
            const uint2* rowp = rbp + (buf*8 + r)*256;
            __half2 U1 = m0v[r];                  // fields >= 0
            __half2 U2 = __floats2half2_rn(0.f, 0.f);
            #pragma unroll
            for (int k = 0; k < 7; k++) {
                uint2 pr = rowp[j0a[k]];
                __half2 a = *(__half2*)&pr.x;
                __half2 b = *(__half2*)&pr.y;
                __half2 v = __hfma2(w2a[k], b, __hmul2(om2a[k], a));
                if (k & 1) U2 = __hmax2(U2, v); else U1 = __hmax2(U1, v);
            }
            float2 uf = __half22float2(__hmax2(U1, U2));
            radp[(y0+r)*NW] = __float2half_rn(uf.x - uf.y);
        }
        if (more && doB) {
            int nbase = (buf^1)*8*256;
            #pragma unroll
            for (int r = 0; r < 8; r++) storev(nbase + r*256, nb[r]);
        }
        __syncthreads();
        buf ^= 1;
    }
}

// --------- K4: 1x1-conv MLP + modulate (2 px/thread, float4 weight loads)
__global__ void __launch_bounds__(256) k_mlp(
    const float* __restrict__ x,
    const float* __restrict__ w1, const float* __restrict__ b1,
    const float* __restrict__ w2, const float* __restrict__ b2,
    float* __restrict__ out)
{
    __shared__ __align__(16) float sw1t[CM*NC];  // transposed: [c][o]
    __shared__ __align__(16) float sw2c[NC*CM];  // [c][o] (native w2 layout)
    __shared__ float sb1[CM], sb2[NC];
    const int tid = threadIdx.x;
    for (int i = tid; i < CM*NC; i += 256) {
        int c = i >> 4, o = i & 15;
        sw1t[i] = w1[o*NC + c];
        sw2c[i] = w2[i];
    }
    if (tid < CM) sb1[tid] = b1[tid];
    if (tid < NC) sb2[tid] = b2[tid];
    __syncthreads();

    int g  = blockIdx.x * 256 + tid;      // pixel-pair index (131072 total)
    int b  = g >> 15;                     // 32768 pairs per batch
    int hw = (g & 32767) << 1;
    size_t base = ((size_t)(b*NC) << 16) + hw;
    const __half2* rp = (const __half2*)(g_rad + base);
    const float2*  xp = (const float2*) (x     + base);
    float2*        op = (float2*)       (out   + base);

    float h0[CM], h1[CM];
    #pragma unroll
    for (int o = 0; o < CM; o++) { h0[o] = sb1[o]; h1[o] = sb1[o]; }
    for (int c = 0; c < NC; c++) {
        float2 r = __half22float2(__ldg(rp + ((size_t)c << 15)));
        const float4* wp = (const float4*)(sw1t + (c << 4));
        #pragma unroll
        for (int q = 0; q < 4; q++) {
            float4 w4 = wp[q];
            h0[q*4+0] = fmaf(w4.x, r.x, h0[q*4+0]); h1[q*4+0] = fmaf(w4.x, r.y, h1[q*4+0]);
            h0[q*4+1] = fmaf(w4.y, r.x, h0[q*4+1]); h1[q*4+1] = fmaf(w4.y, r.y, h1[q*4+1]);
            h0[q*4+2] = fmaf(w4.z, r.x, h0[q*4+2]); h1[q*4+2] = fmaf(w4.z, r.y, h1[q*4+2]);
            h0[q*4+3] = fmaf(w4.w, r.x, h0[q*4+3]); h1[q*4+3] = fmaf(w4.w, r.y, h1[q*4+3]);
        }
    }
    #pragma unroll
    for (int o = 0; o < CM; o++) { h0[o] = fmaxf(h0[o], 0.f); h1[o] = fmaxf(h1[o], 0.f); }
    for (int c = 0; c < NC; c++) {
        float a0 = sb2[c], a1 = sb2[c];
        const float4* wp = (const float4*)(sw2c + (c << 4));
        #pragma unroll
        for (int q = 0; q < 4; q++) {
            float4 w4 = wp[q];
            a0 = fmaf(w4.x, h0[q*4+0], a0); a1 = fmaf(w4.x, h1[q*4+0], a1);
            a0 = fmaf(w4.y, h0[q*4+1], a0); a1 = fmaf(w4.y, h1[q*4+1], a1);
            a0 = fmaf(w4.z, h0[q*4+2], a0); a1 = fmaf(w4.z, h1[q*4+2], a1);
            a0 = fmaf(w4.w, h0[q*4+3], a0); a1 = fmaf(w4.w, h1[q*4+3], a1);
        }
        float2 xv = __ldg(xp + ((size_t)c << 15));
        float2 ov;
        ov.x = xv.x * sigmoid_f(a0);
        ov.y = xv.y * sigmoid_f(a1);
        op[(size_t)c << 15] = ov;
    }
}

extern "C" void kernel_launch(void* const* d_in, const int* in_sizes, int n_in,
                              void* d_out, int out_size) {
    const float* x  = (const float*)d_in[0];
    const float* w1 = (const float*)d_in[1];
    const float* b1 = (const float*)d_in[2];
    const float* w2 = (const float*)d_in[3];
    const float* b2 = (const float*)d_in[4];
    float* out = (float*)d_out;

    cudaFuncSetAttribute(k_pyr,   cudaFuncAttributeMaxDynamicSharedMemorySize, SMEM_PYR);
    cudaFuncSetAttribute(k_field, cudaFuncAttributeMaxDynamicSharedMemorySize, SMEM_RB);

    k_stats<<<NBC, 256>>>(x);
    k_init<<<dim3(8, 8, NBC), 256>>>(x);
    k_pyr<<<NBC, 256, SMEM_PYR>>>();
    k_field<<<NBC, 256, SMEM_RB>>>();
    k_mlp<<<(NB*NHW)/512, 256>>>(x, w1, b1, w2, b2, out);
}

// round 12
// speedup vs baseline: 1.4475x; 1.0335x over previous
#include <cuda_runtime.h>
#include <cuda_fp16.h>
#include <math.h>

#define NB 4
#define NC 128
#define NH 256
#define NW 256
#define NHW (NH*NW)
#define NBC (NB*NC)      // 512 (b,c) planes
#define CM 16
#define PYR_ELEMS 21844  // 128^2+64^2+32^2+16^2+8^2+4^2+2^2

// scratch (device globals: no allocation allowed)
__device__ float   g_thr[2*NBC];
__device__ __half2 g_M0[(size_t)NBC*NHW];        // (pos,neg) packed: max(init, down0)
__device__ __half2 g_r1[(size_t)NBC*128*128];    // resize(down0 -> 128) both signs
__device__ __half2 g_pyrh[(size_t)NBC*PYR_ELEMS];// levels 1..7, half2 (consumer copy)
__device__ __half  g_rad[(size_t)NBC*NHW];       // radiance = Lp - Ln

__device__ __constant__ float c_scf[7] = {
    (float)(127.0/255.0), (float)(63.0/255.0), (float)(31.0/255.0),
    (float)(15.0/255.0),  (float)(7.0/255.0),  (float)(3.0/255.0),
    (float)(1.0/255.0)
};
__device__ __constant__ int c_soff[7] = {0, 0, 4096, 5120, 5376, 5440, 5456}; // spyr offsets (k>=1)

__device__ __forceinline__ float sigmoid_f(float t) { return 1.0f / (1.0f + __expf(-t)); }
// 1-MUFU sigmoid: sigmoid(t) = 0.5*tanh(t/2) + 0.5  (tanh.approx: abs err ~2^-11)
__device__ __forceinline__ float sigmoid_fast(float t) {
    float th;
    asm("tanh.approx.f32 %0, %1;" : "=f"(th) : "f"(0.5f * t));
    return fmaf(0.5f, th, 0.5f);
}

// ------------------------------------------------------------------ K0: stats
__global__ void __launch_bounds__(256) k_stats(const float* __restrict__ x) {
    int plane = blockIdx.x;
    const float4* p = (const float4*)(x + (size_t)plane * NHW);
    float sp = 0.f, s2p = 0.f, sn = 0.f, s2n = 0.f;
    for (int i = threadIdx.x; i < NHW/4; i += 256) {
        float4 v = __ldg(p + i);
        float a;
        a = fmaxf(v.x,0.f); sp += a; s2p = fmaf(a,a,s2p); a = fmaxf(-v.x,0.f); sn += a; s2n = fmaf(a,a,s2n);
        a = fmaxf(v.y,0.f); sp += a; s2p = fmaf(a,a,s2p); a = fmaxf(-v.y,0.f); sn += a; s2n = fmaf(a,a,s2n);
        a = fmaxf(v.z,0.f); sp += a; s2p = fmaf(a,a,s2p); a = fmaxf(-v.z,0.f); sn += a; s2n = fmaf(a,a,s2n);
        a = fmaxf(v.w,0.f); sp += a; s2p = fmaf(a,a,s2p); a = fmaxf(-v.w,0.f); sn += a; s2n = fmaf(a,a,s2n);
    }
    __shared__ float red[8][4];
    #pragma unroll
    for (int o = 16; o; o >>= 1) {
        sp  += __shfl_down_sync(0xffffffffu, sp,  o);
        s2p += __shfl_down_sync(0xffffffffu, s2p, o);
        sn  += __shfl_down_sync(0xffffffffu, sn,  o);
        s2n += __shfl_down_sync(0xffffffffu, s2n, o);
    }
    int lane = threadIdx.x & 31, w = threadIdx.x >> 5;
    if (lane == 0) { red[w][0] = sp; red[w][1] = s2p; red[w][2] = sn; red[w][3] = s2n; }
    __syncthreads();
    if (threadIdx.x == 0) {
        float SP=0,S2P=0,SN=0,S2N=0;
        for (int i = 0; i < 8; i++) { SP+=red[i][0]; S2P+=red[i][1]; SN+=red[i][2]; S2N+=red[i][3]; }
        const float N = (float)NHW;
        float vp = fmaxf((S2P - SP*SP/N) / (N - 1.f), 0.f);
        g_thr[plane]       = SP/N + 2.f * sqrtf(vp);
        float vn = fmaxf((S2N - SN*SN/N) / (N - 1.f), 0.f);
        g_thr[NBC + plane] = SN/N + 2.f * sqrtf(vn);
    }
}

// ------------- K1: init + M0 + r1 samples (half2-packed, separable maxpool)
__global__ void __launch_bounds__(256) k_init(const float* __restrict__ x) {
    __shared__ __half2 sI[35][40];   // masked init, rows/cols (ty0-1.., tx0-1..), 35x35 used
    __shared__ __half2 sR[35][40];   // rowmax3: 35 rows x 33 cols (col c -> global tx0+c)
    __shared__ __half2 sD[33][40];   // down0 = gamma*colmax3: 33x33 (r,c -> ty0+r, tx0+c)
    const int bc  = blockIdx.z;
    const int tx0 = blockIdx.x * 32, ty0 = blockIdx.y * 32;
    const float thp = g_thr[bc], thn = g_thr[NBC + bc];
    const float* xp = x + (size_t)bc * NHW;
    const int tid = threadIdx.x;

    for (int idx = tid; idx < 35*35; idx += 256) {
        int r = idx / 35, c = idx % 35;
        int gy = ty0 - 1 + r; gy = min(max(gy, 0), NH-1);
        int gx = tx0 - 1 + c; gx = min(max(gx, 0), NW-1);
        float v  = __ldg(xp + gy*NW + gx);
        float vp = fmaxf(v, 0.f);
        float vn = fmaxf(-v, 0.f);
        float ipv = vp * (sigmoid_fast(100.f*(vp - thp)) + 1e-6f);
        float inv = vn * (sigmoid_fast(100.f*(vn - thn)) + 1e-6f);
        sI[r][c] = __floats2half2_rn(ipv, inv);
    }
    __syncthreads();
    for (int idx = tid; idx < 35*33; idx += 256) {
        int r = idx / 33, c = idx % 33;
        sR[r][c] = __hmax2(__hmax2(sI[r][c], sI[r][c+1]), sI[r][c+2]);
    }
    __syncthreads();
    for (int idx = tid; idx < 33*33; idx += 256) {
        int r = idx / 33, c = idx % 33;
        __half2 m = __hmax2(__hmax2(sR[r][c], sR[r+1][c]), sR[r+2][c]);
        float2 mf = __half22float2(m);
        sD[r][c] = __floats2half2_rn(0.99f*mf.x, 0.99f*mf.y);
    }
    __syncthreads();
    for (int idx = tid; idx < 32*32; idx += 256) {
        int r = idx >> 5, c = idx & 31;
        g_M0[(size_t)bc*NHW + (size_t)(ty0+r)*NW + (tx0+c)] =
            __hmax2(sI[r+1][c+1], sD[r][c]);
    }
    // r1 = resize(down0 -> 128, align_corners). Tile owns (i,j) iff floor(i*A1)
    // in [ty0,ty0+31] and floor(j*A1) in [tx0,tx0+31] (same fp expr as below).
    const float A1 = 255.0f / 127.0f;
    int i_lo = max(0, (int)((float)ty0 / A1) - 1);
    while (i_lo < 128 && (int)((float)i_lo * A1) < ty0) i_lo++;
    int i_hi = min(127, (int)((float)(ty0+32) / A1) + 1);
    while (i_hi >= i_lo && (int)((float)i_hi * A1) > ty0+31) i_hi--;
    int j_lo = max(0, (int)((float)tx0 / A1) - 1);
    while (j_lo < 128 && (int)((float)j_lo * A1) < tx0) j_lo++;
    int j_hi = min(127, (int)((float)(tx0+32) / A1) + 1);
    while (j_hi >= j_lo && (int)((float)j_hi * A1) > tx0+31) j_hi--;
    int ni = i_hi - i_lo + 1; if (ni < 0) ni = 0;
    int nj = j_hi - j_lo + 1; if (nj < 0) nj = 0;
    for (int idx = tid; idx < ni*nj; idx += 256) {
        int i = i_lo + idx / nj;
        int j = j_lo + idx % nj;
        float fy = (float)i * A1; int i0 = (int)fy; float wy = fy - (float)i0;
        int i1 = min(i0 + 1, NH-1);
        float fx = (float)j * A1; int j0 = (int)fx; float wx = fx - (float)j0;
        int j1 = min(j0 + 1, NW-1);
        int li0 = i0 - ty0, li1 = i1 - ty0, lj0 = j0 - tx0, lj1 = j1 - tx0;
        float2 a = __half22float2(sD[li0][lj0]);
        float2 b = __half22float2(sD[li0][lj1]);
        float2 c2 = __half22float2(sD[li1][lj0]);
        float2 d = __half22float2(sD[li1][lj1]);
        float vp = (1.f-wy)*((1.f-wx)*a.x + wx*b.x) + wy*((1.f-wx)*c2.x + wx*d.x);
        float vn = (1.f-wy)*((1.f-wx)*a.y + wx*b.y) + wy*((1.f-wx)*c2.y + wx*d.y);
        g_r1[(size_t)bc*16384 + i*128 + j] = __floats2half2_rn(vp, vn);
    }
}

// ------- K2: pyramid levels 1..7, fp32 chain entirely in smem, only half2 to gmem
#define SMEM_PYR (16384*4 + 16384*8)   // T: 64 KB staging/scratch, A: 131 KB chain
__global__ void __launch_bounds__(512) k_pyr() {
    extern __shared__ unsigned char smraw[];
    __half2* S = (__half2*)smraw;                 // r1 staging (phase 1 only)
    float2*  T = (float2*)smraw;                  // scratch view: resize outputs (<=64^2)
    float2*  A = (float2*)(smraw + 16384*4);      // current level, fp32 chain
    const int bc = blockIdx.x, tid = threadIdx.x;
    const __half2* r1p = g_r1 + (size_t)bc * 16384;
    __half2* pyrh = g_pyrh + (size_t)bc * PYR_ELEMS;

    for (int i = tid; i < 16384; i += 512) S[i] = __ldg(r1p + i);
    __syncthreads();
    // level 1 (size 128): down1 = gamma^2 * maxpool3(r1) -> A, pyrh
    for (int idx = tid; idx < 16384; idx += 512) {
        int i = idx >> 7, j = idx & 127;
        float mp = 0.f, mn = 0.f;
        #pragma unroll
        for (int dr = -1; dr <= 1; dr++) {
            int ii = min(max(i+dr,0),127) << 7;
            #pragma unroll
            for (int dc = -1; dc <= 1; dc++) {
                int jj = min(max(j+dc,0),127);
                float2 v = __half22float2(S[ii + jj]);
                mp = fmaxf(mp, v.x); mn = fmaxf(mn, v.y);
            }
        }
        float op = 0.9801f*mp, on = 0.9801f*mn;
        A[idx]    = make_float2(op, on);
        pyrh[idx] = __floats2half2_rn(op, on);
    }
    __syncthreads();
    int off_out = 16384, sin = 128;
    double gd = 0.9801;
    for (int k = 2; k <= 7; k++) {
        int sout = sin >> 1;
        float ak = (float)((double)(sin-1) / (double)(sout-1));
        // resize A (sin^2) -> T (sout^2); S/r1 staging is dead by now
        for (int idx = tid; idx < sout*sout; idx += 512) {
            int i = idx / sout, j = idx % sout;
            float fy = (float)i * ak; int i0 = (int)fy; float wy = fy - (float)i0; int i1 = min(i0+1, sin-1);
            float fx = (float)j * ak; int j0 = (int)fx; float wx = fx - (float)j0; int j1 = min(j0+1, sin-1);
            float2 a = A[i0*sin+j0], b = A[i0*sin+j1], c = A[i1*sin+j0], d = A[i1*sin+j1];
            T[idx] = make_float2(
                (1.f-wy)*((1.f-wx)*a.x + wx*b.x) + wy*((1.f-wx)*c.x + wx*d.x),
                (1.f-wy)*((1.f-wx)*a.y + wx*b.y) + wy*((1.f-wx)*c.y + wx*d.y));
        }
        __syncthreads();
        gd *= gd;                         // gamma^(2^k)
        float gk = (float)gd;
        // pool T -> A (overwrite head) + pyrh
        for (int idx = tid; idx < sout*sout; idx += 512) {
            int i = idx / sout, j = idx % sout;
            float mp = 0.f, mn = 0.f;
            #pragma unroll
            for (int dr = -1; dr <= 1; dr++) {
                int ii = min(max(i+dr,0),sout-1) * sout;
                #pragma unroll
                for (int dc = -1; dc <= 1; dc++) {
                    int jj = min(max(j+dc,0),sout-1);
                    float2 v = T[ii + jj];
                    mp = fmaxf(mp, v.x); mn = fmaxf(mn, v.y);
                }
            }
            float op = gk*mp, on = gk*mn;
            A[idx] = make_float2(op, on);
            pyrh[off_out + idx] = __floats2half2_rn(op, on);
        }
        __syncthreads();
        off_out += sout*sout; sin = sout;
    }
}

// ----- K3: radiance. Pair-packed rowbuf: 1 LDS.64 per level per pixel (7 total)
#define SMEM_RB (2*8*256*8)   // [2 buf][8 rows][256 pair slots] of uint2
__global__ void __launch_bounds__(256, 4) k_field() {
    __shared__ __half2 spyr[5460];       // levels 2..7 (64^2..2^2)
    extern __shared__ uint2 rbp[];       // pair rowbuf: slot j = (v[j], v[j+1])
    unsigned* rbw = (unsigned*)rbp;      // 32-bit view for builders
    const int bc  = blockIdx.x;
    const int tid = threadIdx.x;
    const __half2* pyrh = g_pyrh + (size_t)bc * PYR_ELEMS;
    for (int i = tid; i < 5460; i += 256) spyr[i] = __ldg(&pyrh[16384 + i]);

    // consume constants: pair-slot index per level (taps come as one LDS.64)
    const int rboff[7] = {0, 128, 192, 224, 240, 248, 252};
    int j0a[7]; __half2 w2a[7], om2a[7];
    #pragma unroll
    for (int k = 0; k < 7; k++) {
        float fx = (float)tid * c_scf[k];
        int j0 = (int)fx; float wx = fx - (float)j0;
        j0a[k] = rboff[k] + j0;
        w2a[k]  = __floats2half2_rn(wx, wx);
        om2a[k] = __floats2half2_rn(1.f-wx, 1.f-wx);
    }

    // build constants: thread tid builds value at (level kb, index jb)
    int kb, jb;
    if      (tid < 128) { kb = 0; jb = tid;       }
    else if (tid < 192) { kb = 1; jb = tid - 128; }
    else if (tid < 224) { kb = 2; jb = tid - 192; }
    else if (tid < 240) { kb = 3; jb = tid - 224; }
    else if (tid < 248) { kb = 4; jb = tid - 240; }
    else if (tid < 252) { kb = 5; jb = tid - 248; }
    else                { kb = 6; jb = tid - 252; }
    const bool doB = (tid < 254);
    const int   sb   = 128 >> kb;
    const float scb  = c_scf[kb];
    const int   sob  = c_soff[kb];
    const int   bpos = rboff[kb] + jb;      // pair-slot this thread owns (lo half)
    const bool  isLast = (jb == sb-1);
    __syncthreads();   // spyr visible

    // y-lerped value (half2 math) for output row y at (kb, jb)
    auto buildv = [&](int y) -> unsigned {
        float fy = (float)y * scb;
        int i0 = (int)fy; float wy = fy - (float)i0; int i1 = min(i0+1, sb-1);
        __half2 a, b;
        if (kb == 0) { a = __ldg(&pyrh[i0*128 + jb]); b = __ldg(&pyrh[i1*128 + jb]); }
        else         { a = spyr[sob + i0*sb + jb];    b = spyr[sob + i1*sb + jb];    }
        __half2 v = __hfma2(__float2half2_rn(wy), b,
                            __hmul2(__float2half2_rn(1.f-wy), a));
        return *(unsigned*)&v;
    };
    // write v into pair slots: own .lo, previous slot's .hi, clamp dup at edge
    auto storev = [&](int rowbase /*pairs*/, unsigned vb) {
        int w = (rowbase + bpos) * 2;
        rbw[w] = vb;
        if (jb > 0)  rbw[w - 1] = vb;      // (bpos-1).hi
        if (isLast)  rbw[w + 1] = vb;      // own .hi (j1 clamp)
    };

    // prologue: rows 0..7 into buffer 0
    if (doB) {
        #pragma unroll
        for (int r = 0; r < 8; r++) storev(r*256, buildv(r));
    }
    __syncthreads();

    const __half2* M0p = g_M0 + (size_t)bc * NHW + tid;
    __half* radp = g_rad + (size_t)bc * NHW + tid;

    int buf = 0;
    for (int y0 = 0; y0 < NH; y0 += 8) {
        // batch-issue this block's 8 M0 loads (MLP=8 hides L2/DRAM latency)
        __half2 m0v[8];
        #pragma unroll
        for (int r = 0; r < 8; r++) m0v[r] = __ldg(M0p + (y0+r)*NW);
        // prefetch next block's build values (loads overlap consume below)
        unsigned nb[8];
        const bool more = (y0 + 8 < NH);
        if (more && doB) {
            #pragma unroll
            for (int r = 0; r < 8; r++) nb[r] = buildv(y0 + 8 + r);
        }
        // consume 8 rows at column tid; two accumulators for ILP
        #pragma unroll
        for (int r = 0; r < 8; r++) {
            const uint2* rowp = rbp + (buf*8 + r)*256;
            __half2 U1 = m0v[r];                  // fields >= 0
            __half2 U2 = __floats2half2_rn(0.f, 0.f);
            #pragma unroll
            for (int k = 0; k < 7; k++) {
                uint2 pr = rowp[j0a[k]];
                __half2 a = *(__half2*)&pr.x;
                __half2 b = *(__half2*)&pr.y;
                __half2 v = __hfma2(w2a[k], b, __hmul2(om2a[k], a));
                if (k & 1) U2 = __hmax2(U2, v); else U1 = __hmax2(U1, v);
            }
            float2 uf = __half22float2(__hmax2(U1, U2));
            radp[(y0+r)*NW] = __float2half_rn(uf.x - uf.y);
        }
        if (more && doB) {
            int nbase = (buf^1)*8*256;
            #pragma unroll
            for (int r = 0; r < 8; r++) storev(nbase + r*256, nb[r]);
        }
        __syncthreads();
        buf ^= 1;
    }
}

// --------- K4: 1x1-conv MLP + modulate (2 px/thread, float4 weight loads)
__global__ void __launch_bounds__(256) k_mlp(
    const float* __restrict__ x,
    const float* __restrict__ w1, const float* __restrict__ b1,
    const float* __restrict__ w2, const float* __restrict__ b2,
    float* __restrict__ out)
{
    __shared__ __align__(16) float sw1t[CM*NC];  // transposed: [c][o]
    __shared__ __align__(16) float sw2c[NC*CM];  // [c][o] (native w2 layout)
    __shared__ float sb1[CM], sb2[NC];
    const int tid = threadIdx.x;
    for (int i = tid; i < CM*NC; i += 256) {
        int c = i >> 4, o = i & 15;
        sw1t[i] = w1[o*NC + c];
        sw2c[i] = w2[i];
    }
    if (tid < CM) sb1[tid] = b1[tid];
    if (tid < NC) sb2[tid] = b2[tid];
    __syncthreads();

    int g  = blockIdx.x * 256 + tid;      // pixel-pair index (131072 total)
    int b  = g >> 15;                     // 32768 pairs per batch
    int hw = (g & 32767) << 1;
    size_t base = ((size_t)(b*NC) << 16) + hw;
    const __half2* rp = (const __half2*)(g_rad + base);
    const float2*  xp = (const float2*) (x     + base);
    float2*        op = (float2*)       (out   + base);

    float h0[CM], h1[CM];
    #pragma unroll
    for (int o = 0; o < CM; o++) { h0[o] = sb1[o]; h1[o] = sb1[o]; }
    for (int c = 0; c < NC; c++) {
        float2 r = __half22float2(__ldg(rp + ((size_t)c << 15)));
        const float4* wp = (const float4*)(sw1t + (c << 4));
        #pragma unroll
        for (int q = 0; q < 4; q++) {
            float4 w4 = wp[q];
            h0[q*4+0] = fmaf(w4.x, r.x, h0[q*4+0]); h1[q*4+0] = fmaf(w4.x, r.y, h1[q*4+0]);
            h0[q*4+1] = fmaf(w4.y, r.x, h0[q*4+1]); h1[q*4+1] = fmaf(w4.y, r.y, h1[q*4+1]);
            h0[q*4+2] = fmaf(w4.z, r.x, h0[q*4+2]); h1[q*4+2] = fmaf(w4.z, r.y, h1[q*4+2]);
            h0[q*4+3] = fmaf(w4.w, r.x, h0[q*4+3]); h1[q*4+3] = fmaf(w4.w, r.y, h1[q*4+3]);
        }
    }
    #pragma unroll
    for (int o = 0; o < CM; o++) { h0[o] = fmaxf(h0[o], 0.f); h1[o] = fmaxf(h1[o], 0.f); }
    for (int c = 0; c < NC; c++) {
        float a0 = sb2[c], a1 = sb2[c];
        const float4* wp = (const float4*)(sw2c + (c << 4));
        #pragma unroll
        for (int q = 0; q < 4; q++) {
            float4 w4 = wp[q];
            a0 = fmaf(w4.x, h0[q*4+0], a0); a1 = fmaf(w4.x, h1[q*4+0], a1);
            a0 = fmaf(w4.y, h0[q*4+1], a0); a1 = fmaf(w4.y, h1[q*4+1], a1);
            a0 = fmaf(w4.z, h0[q*4+2], a0); a1 = fmaf(w4.z, h1[q*4+2], a1);
            a0 = fmaf(w4.w, h0[q*4+3], a0); a1 = fmaf(w4.w, h1[q*4+3], a1);
        }
        float2 xv = __ldg(xp + ((size_t)c << 15));
        float2 ov;
        ov.x = xv.x * sigmoid_fast(a0);
        ov.y = xv.y * sigmoid_fast(a1);
        op[(size_t)c << 15] = ov;
    }
}

extern "C" void kernel_launch(void* const* d_in, const int* in_sizes, int n_in,
                              void* d_out, int out_size) {
    const float* x  = (const float*)d_in[0];
    const float* w1 = (const float*)d_in[1];
    const float* b1 = (const float*)d_in[2];
    const float* w2 = (const float*)d_in[3];
    const float* b2 = (const float*)d_in[4];
    float* out = (float*)d_out;

    cudaFuncSetAttribute(k_pyr,   cudaFuncAttributeMaxDynamicSharedMemorySize, SMEM_PYR);
    cudaFuncSetAttribute(k_field, cudaFuncAttributeMaxDynamicSharedMemorySize, SMEM_RB);

    k_stats<<<NBC, 256>>>(x);
    k_init<<<dim3(8, 8, NBC), 256>>>(x);
    k_pyr<<<NBC, 512, SMEM_PYR>>>();
    k_field<<<NBC, 256, SMEM_RB>>>();
    k_mlp<<<(NB*NHW)/512, 256>>>(x, w1, b1, w2, b2, out);
}